// round 4
// baseline (speedup 1.0000x reference)
#include <cuda_runtime.h>
#include <math.h>

// R4: resubmit of R3 (infra failure, no kernel signal).
// Point-pair f32x2 packing. Each thread owns 2 adjacent points; shared holds
// duplicated coefficient pairs so one LDS.128 feeds two FFMA2
// (4 outputs / LDS instr, vs 2 in R2 which was LDS-bound at L1=86%).

#define NPTS    110592
#define NB      30
#define NOI     256
#define NQH     64              // channel-pairs per half (128 channels / half)
#define THREADS 128

struct WParams { float w[NB]; };

__device__ __forceinline__ void basis_eval(float r, float th, float ph,
                                           float* __restrict__ bas)
{
    const float ct  = cosf(th);
    const float st2 = fmaxf(1.0f - ct * ct, 0.0f);
    const float st  = sqrtf(st2);
    const float cp  = cosf(ph);
    const float sp  = sinf(ph);
    const float c2p = cp * cp - sp * sp;
    const float s2p = 2.0f * sp * cp;
    const float c3p = c2p * cp - s2p * sp;
    const float s3p = s2p * cp + c2p * sp;

    const float er1 = expf(-r);
    const float er2 = expf(-0.5f * r);
    const float er3 = expf(-0.33333333333333333f * r);
    const float er4 = expf(-0.25f * r);
    const float rho3 = 0.66666666666666666f * r;
    const float rho4 = 0.5f * r;

    const float F10 = er1;
    const float F20 = er2 * (2.0f - r);
    const float F21 = er2 * r;
    const float F30 = er3 * (3.0f + rho3 * (-3.0f + 0.5f * rho3));
    const float F31 = er3 * rho3 * (4.0f - rho3);
    const float F32 = er3 * rho3 * rho3;
    const float F40 = er4 * (4.0f + rho4 * (-6.0f + rho4 * (2.0f - 0.16666666666666666f * rho4)));
    const float F41 = er4 * rho4 * (10.0f + rho4 * (-5.0f + 0.5f * rho4));
    const float F42 = er4 * rho4 * rho4 * (6.0f - rho4);
    const float F43 = er4 * rho4 * rho4 * rho4;

    const float p10 = ct;
    const float p11 = -st;
    const float p20 = 1.5f * ct * ct - 0.5f;
    const float p21 = -3.0f * ct * st;
    const float p22 = 3.0f * st2;
    const float p30 = (2.5f * ct * ct - 1.5f) * ct;
    const float p31 = (1.5f - 7.5f * ct * ct) * st;
    const float p32 = 15.0f * ct * st2;
    const float p33 = -15.0f * st * st2;

    bas[0]  = F10;
    bas[1]  = F20;
    bas[2]  = F21 * p11 * sp;
    bas[3]  = F21 * p10;
    bas[4]  = F21 * p11 * cp;
    bas[5]  = F30;
    bas[6]  = F31 * p11 * sp;
    bas[7]  = F31 * p10;
    bas[8]  = F31 * p11 * cp;
    bas[9]  = F32 * p22 * s2p;
    bas[10] = F32 * p21 * sp;
    bas[11] = F32 * p20;
    bas[12] = F32 * p21 * cp;
    bas[13] = F32 * p22 * c2p;
    bas[14] = F40;
    bas[15] = F41 * p11 * sp;
    bas[16] = F41 * p10;
    bas[17] = F41 * p11 * cp;
    bas[18] = F42 * p22 * s2p;
    bas[19] = F42 * p21 * sp;
    bas[20] = F42 * p20;
    bas[21] = F42 * p21 * cp;
    bas[22] = F42 * p22 * c2p;
    bas[23] = F43 * p33 * s3p;
    bas[24] = F43 * p32 * s2p;
    bas[25] = F43 * p31 * sp;
    bas[26] = F43 * p30;
    bas[27] = F43 * p31 * cp;
    bas[28] = F43 * p32 * c2p;
    bas[29] = F43 * p33 * c3p;
}

__global__ __launch_bounds__(THREADS, 2)
void dcconv_basis_expand2(const float* __restrict__ pos,
                          const float* __restrict__ coef,
                          float* __restrict__ out,
                          WParams W)
{
    // sc2[b*NQH + q] = { (w*c[ch0], w*c[ch0]) , (w*c[ch1], w*c[ch1]) }
    // for channels ch0 = half*128 + 2q, ch1 = ch0+1. 30*64*16 = 30720 B.
    __shared__ ulonglong2 sc2[NB * NQH];

    const int tid = threadIdx.x;
    const int p0  = (blockIdx.x * THREADS + tid) * 2;   // two adjacent points

    // position loads as three float2 (8B-aligned: 3*p0 is even)
    const float2* pp = (const float2*)(pos + 3 * p0);
    const float2 f0 = pp[0];   // r0, th0
    const float2 f1 = pp[1];   // ph0, r1
    const float2 f2 = pp[2];   // th1, ph1

    float bas0[NB], bas1[NB];
    basis_eval(f0.x, f0.y, f1.x, bas0);
    basis_eval(f1.y, f2.x, f2.y, bas1);

    // pack point-pair into f32x2 registers
    unsigned long long b2[NB];
#pragma unroll
    for (int b = 0; b < NB; ++b)
        asm("mov.b64 %0, {%1, %2};" : "=l"(b2[b]) : "f"(bas0[b]), "f"(bas1[b]));

    unsigned long long* obase = (unsigned long long*)(out + p0);

#pragma unroll
    for (int half = 0; half < 2; ++half) {
        __syncthreads();   // protect sc2 reuse across halves
        // fill duplicated coefficient table for channels [half*128, half*128+128)
        for (int i = tid; i < NB * NQH; i += THREADS) {
            const int b  = i / NQH;
            const int q  = i % NQH;
            const int ch = half * 128 + 2 * q;
            const float wb = W.w[b];
            const float lo = coef[ch * NB + b] * wb;
            const float hi = coef[(ch + 1) * NB + b] * wb;
            unsigned long long dlo, dhi;
            asm("mov.b64 %0, {%1, %1};" : "=l"(dlo) : "f"(lo));
            asm("mov.b64 %0, {%1, %1};" : "=l"(dhi) : "f"(hi));
            sc2[i] = make_ulonglong2(dlo, dhi);
        }
        __syncthreads();

        // offset in u64 units: out index (ch*NPTS + p0)/2
        unsigned long long* o = obase + (size_t)(half * 128) * (NPTS / 2);
#pragma unroll 2
        for (int q = 0; q < NQH; ++q) {
            unsigned long long a0 = 0ULL, a1 = 0ULL;   // (p0, p1) accumulators
#pragma unroll
            for (int b = 0; b < NB; ++b) {
                const ulonglong2 cc = sc2[b * NQH + q];   // LDS.128 broadcast
                asm("fma.rn.f32x2 %0, %1, %2, %0;" : "+l"(a0) : "l"(b2[b]), "l"(cc.x));
                asm("fma.rn.f32x2 %0, %1, %2, %0;" : "+l"(a1) : "l"(b2[b]), "l"(cc.y));
            }
            o[0]        = a0;   // channel 2q,   points p0,p0+1  (STG.64)
            o[NPTS / 2] = a1;   // channel 2q+1
            o += NPTS;          // advance 2 channels (in u64 units: 2*NPTS/2)
        }
    }
}

extern "C" void kernel_launch(void* const* d_in, const int* in_sizes, int n_in,
                              void* d_out, int out_size)
{
    const float* pos  = (const float*)d_in[0];
    const float* coef = (const float*)d_in[1];
    if (n_in >= 2 && in_sizes[0] == NOI * NB) {
        coef = (const float*)d_in[0];
        pos  = (const float*)d_in[1];
    }

    const double PI  = 3.14159265358979323846;
    const double K00 = sqrt(1.0 / (4.0 * PI));
    const double K10 = sqrt(3.0 / (4.0 * PI));
    const double K20 = sqrt(5.0 / (4.0 * PI));
    const double K30 = sqrt(7.0 / (4.0 * PI));
    const double A11 = sqrt(3.0 / (4.0 * PI));
    const double A21 = sqrt(5.0 / (12.0 * PI));
    const double A22 = sqrt(5.0 / (48.0 * PI));
    const double A31 = sqrt(7.0 / (24.0 * PI));
    const double A32 = sqrt(7.0 / (240.0 * PI));
    const double A33 = sqrt(7.0 / (1440.0 * PI));

    const double C10 = 2.0;
    const double C20 = sqrt(1.0 / 8.0);
    const double C21 = sqrt(1.0 / 24.0);
    const double C30 = sqrt(16.0 / 972.0);
    const double C31 = sqrt(8.0 / 3888.0);
    const double C32 = sqrt(8.0 / 19440.0);
    const double C40 = sqrt(6.0 / 1536.0);
    const double C41 = sqrt(2.0 / 7680.0);
    const double C42 = sqrt(1.0 / 46080.0);
    const double C43 = sqrt(1.0 / 322560.0);

    WParams W;
    const double w[NB] = {
        C10 * K00,
        C20 * K00,
        C21 * A11, C21 * K10, C21 * A11,
        C30 * K00,
        C31 * A11, C31 * K10, C31 * A11,
        C32 * A22, C32 * A21, C32 * K20, C32 * A21, C32 * A22,
        C40 * K00,
        C41 * A11, C41 * K10, C41 * A11,
        C42 * A22, C42 * A21, C42 * K20, C42 * A21, C42 * A22,
        C43 * A33, C43 * A32, C43 * A31, C43 * K30,
        C43 * A31, C43 * A32, C43 * A33
    };
    for (int i = 0; i < NB; ++i) W.w[i] = (float)w[i];

    dcconv_basis_expand2<<<NPTS / (2 * THREADS), THREADS>>>(pos, coef, (float*)d_out, W);
    (void)out_size;
}